// round 1
// baseline (speedup 1.0000x reference)
#include <cuda_runtime.h>
#include <math.h>

#define NN 100000
#define EE 1600000
#define FNODE 79
#define FEDGE 10

// ---------------- scratch (device globals; no allocation) ----------------
__device__ float g_xl[NN * 128];
__device__ float g_xr[NN * 128];
__device__ float g_agg[NN * 128];
__device__ float g_h[NN * 64];
__device__ float g_ex[EE * 2];   // logits, then exp values (in place)
__device__ int   g_mx[NN * 2];   // ordered-int encoded max
__device__ float g_den[NN * 2];

// order-preserving float<->int mapping for atomicMax on float
__device__ __forceinline__ int f2o(float f) {
    int i = __float_as_int(f);
    return (i >= 0) ? i : (i ^ 0x7FFFFFFF);
}
__device__ __forceinline__ float o2f(int i) {
    return __int_as_float((i >= 0) ? i : (i ^ 0x7FFFFFFF));
}

// ---------------- init: zero agg/den, mx = enc(-inf) ----------------
__global__ void init_kernel(float* agg, int aggN, int* mx, float* den) {
    int stride = gridDim.x * blockDim.x;
    int i0 = blockIdx.x * blockDim.x + threadIdx.x;
    int neg_inf_enc = f2o(-__int_as_float(0x7F800000));
    for (int i = i0; i < aggN; i += stride) agg[i] = 0.f;
    for (int i = i0; i < NN * 2; i += stride) { mx[i] = neg_inf_enc; den[i] = 0.f; }
}

// ---------------- node transforms: xl = act(in)@Wl + bl ; xr likewise ----------------
#define TN 32
__global__ void transform_kernel(const float* __restrict__ in, int in_dim, int act,
                                 const float* __restrict__ Wl, const float* __restrict__ bl,
                                 const float* __restrict__ Wr, const float* __restrict__ br,
                                 int out_dim,
                                 float* __restrict__ xl, float* __restrict__ xr) {
    __shared__ float s_in[TN][FNODE + 1];
    int node0 = blockIdx.x * TN;
    int t = threadIdx.x;  // one output column per thread (blockDim.x == out_dim)

    int tot = TN * in_dim;
    for (int idx = t; idx < tot; idx += blockDim.x) {
        int n = idx / in_dim;
        int k = idx - n * in_dim;
        int g = node0 + n;
        float v = (g < NN) ? in[(size_t)g * in_dim + k] : 0.f;
        if (act) v = (v > 0.f) ? v : 0.01f * v;
        s_in[n][k] = v;
    }
    __syncthreads();

    float accl[TN], accr[TN];
    float blv = bl[t], brv = br[t];
#pragma unroll
    for (int n = 0; n < TN; n++) { accl[n] = blv; accr[n] = brv; }

    for (int k = 0; k < in_dim; k++) {
        float wl = Wl[k * out_dim + t];
        float wr = Wr[k * out_dim + t];
#pragma unroll
        for (int n = 0; n < TN; n++) {
            float v = s_in[n][k];
            accl[n] = fmaf(v, wl, accl[n]);
            accr[n] = fmaf(v, wr, accr[n]);
        }
    }
#pragma unroll
    for (int n = 0; n < TN; n++) {
        int g = node0 + n;
        if (g < NN) {
            xl[(size_t)g * out_dim + t] = accl[n];
            xr[(size_t)g * out_dim + t] = accr[n];
        }
    }
}

// ---------------- per-edge attention logits + segment max ----------------
// one warp per edge; ef computed on the fly from edge_attr @ We
__global__ void edge_logit_kernel(const float* __restrict__ xl, const float* __restrict__ xr,
                                  const int* __restrict__ src, const int* __restrict__ dst,
                                  const float* __restrict__ ea,
                                  const float* __restrict__ We, const float* __restrict__ att,
                                  int HC, int C,
                                  float* __restrict__ logit, int* __restrict__ mx) {
    __shared__ float s_We[FEDGE * 128];
    __shared__ float s_att[128];
    int t = threadIdx.x;
    for (int i = t; i < FEDGE * HC; i += blockDim.x) s_We[i] = We[i];
    for (int i = t; i < HC; i += blockDim.x) s_att[i] = att[i];
    __syncthreads();

    int e = (blockIdx.x * blockDim.x + t) >> 5;
    int lane = t & 31;
    if (e >= EE) return;

    int s = src[e], d = dst[e];
    float a[FEDGE];
#pragma unroll
    for (int k = 0; k < FEDGE; k++) a[k] = ea[(size_t)e * FEDGE + k];

    float p0 = 0.f, p1 = 0.f;
    for (int c = lane; c < HC; c += 32) {
        float ef = 0.f;
#pragma unroll
        for (int k = 0; k < FEDGE; k++) ef = fmaf(a[k], s_We[k * HC + c], ef);
        float m = xl[(size_t)s * HC + c] + xr[(size_t)d * HC + c] + ef;
        m = (m > 0.f) ? m : 0.2f * m;  // GATv2 attention leaky relu
        float contrib = m * s_att[c];  // att flattened [H*C] matches column index
        if (c < C) p0 += contrib; else p1 += contrib;
    }
#pragma unroll
    for (int o = 16; o > 0; o >>= 1) {
        p0 += __shfl_xor_sync(0xffffffffu, p0, o);
        p1 += __shfl_xor_sync(0xffffffffu, p1, o);
    }
    if (lane == 0) {
        logit[e * 2]     = p0;
        logit[e * 2 + 1] = p1;
        atomicMax(&mx[d * 2],     f2o(p0));
        atomicMax(&mx[d * 2 + 1], f2o(p1));
    }
}

// ---------------- exp(logit - max) + segment sum ----------------
__global__ void exp_kernel(const int* __restrict__ dst,
                           const int* __restrict__ mx,
                           float* __restrict__ ex, float* __restrict__ den) {
    int i = blockIdx.x * blockDim.x + threadIdx.x;
    if (i >= EE * 2) return;
    int e = i >> 1, h = i & 1;
    int d = dst[e];
    float m = o2f(mx[d * 2 + h]);
    float v = expf(ex[i] - m);
    ex[i] = v;
    atomicAdd(&den[d * 2 + h], v);
}

// ---------------- aggregation: agg[dst] += xl[src] * alpha ----------------
__global__ void agg_kernel(const float* __restrict__ xl,
                           const int* __restrict__ src, const int* __restrict__ dst,
                           const float* __restrict__ ex, const float* __restrict__ den,
                           int HC, int C, float* __restrict__ agg) {
    int e = (blockIdx.x * blockDim.x + threadIdx.x) >> 5;
    int lane = threadIdx.x & 31;
    if (e >= EE) return;
    int s = src[e], d = dst[e];
    float a0 = ex[e * 2]     / fmaxf(den[d * 2],     1e-16f);
    float a1 = ex[e * 2 + 1] / fmaxf(den[d * 2 + 1], 1e-16f);
    for (int c = lane; c < HC; c += 32) {
        float alpha = (c < C) ? a0 : a1;
        atomicAdd(&agg[(size_t)d * HC + c], xl[(size_t)s * HC + c] * alpha);
    }
}

// ---------------- finalize ----------------
__global__ void finalize_concat(const float* __restrict__ agg, const float* __restrict__ bias,
                                float* __restrict__ out) {  // HC = 64, concat
    int i = blockIdx.x * blockDim.x + threadIdx.x;
    if (i >= NN * 64) return;
    out[i] = agg[i] + bias[i & 63];
}

__global__ void finalize_mean(const float* __restrict__ agg, const float* __restrict__ bias,
                              float* __restrict__ out) {  // HC = 128 -> mean over 2 heads
    int i = blockIdx.x * blockDim.x + threadIdx.x;
    if (i >= NN * 64) return;
    int n = i >> 6, c = i & 63;
    out[i] = 0.5f * (agg[(size_t)n * 128 + c] + agg[(size_t)n * 128 + 64 + c]) + bias[c];
}

// ---------------- launch ----------------
extern "C" void kernel_launch(void* const* d_in, const int* in_sizes, int n_in,
                              void* d_out, int out_size) {
    const float* x    = (const float*)d_in[0];
    const int*   ei   = (const int*)d_in[1];
    const float* ea   = (const float*)d_in[2];
    const float* Wl0  = (const float*)d_in[3];
    const float* bl0  = (const float*)d_in[4];
    const float* Wr0  = (const float*)d_in[5];
    const float* br0  = (const float*)d_in[6];
    const float* We0  = (const float*)d_in[7];
    const float* att0 = (const float*)d_in[8];
    const float* bias0= (const float*)d_in[9];
    const float* Wl1  = (const float*)d_in[10];
    const float* bl1  = (const float*)d_in[11];
    const float* Wr1  = (const float*)d_in[12];
    const float* br1  = (const float*)d_in[13];
    const float* We1  = (const float*)d_in[14];
    const float* att1 = (const float*)d_in[15];
    const float* bias1= (const float*)d_in[16];

    const int* src = ei;
    const int* dst = ei + EE;

    float *xl, *xr, *agg, *h, *ex, *den;
    int* mx;
    cudaGetSymbolAddress((void**)&xl,  g_xl);
    cudaGetSymbolAddress((void**)&xr,  g_xr);
    cudaGetSymbolAddress((void**)&agg, g_agg);
    cudaGetSymbolAddress((void**)&h,   g_h);
    cudaGetSymbolAddress((void**)&ex,  g_ex);
    cudaGetSymbolAddress((void**)&mx,  g_mx);
    cudaGetSymbolAddress((void**)&den, g_den);

    const int nodeBlocks = (NN + TN - 1) / TN;          // 3125
    const int edgeBlocks = (EE + 7) / 8;                // warp per edge, 8 warps/block
    const int expBlocks  = (EE * 2 + 255) / 256;
    const int finBlocks  = (NN * 64 + 255) / 256;

    // ---------- layer 0: GATv2(79 -> 32, H=2, concat) -> width 64 ----------
    init_kernel<<<2048, 256>>>(agg, NN * 64, mx, den);
    transform_kernel<<<nodeBlocks, 64>>>(x, FNODE, 0, Wl0, bl0, Wr0, br0, 64, xl, xr);
    edge_logit_kernel<<<edgeBlocks, 256>>>(xl, xr, src, dst, ea, We0, att0, 64, 32, ex, mx);
    exp_kernel<<<expBlocks, 256>>>(dst, mx, ex, den);
    agg_kernel<<<edgeBlocks, 256>>>(xl, src, dst, ex, den, 64, 32, agg);
    finalize_concat<<<finBlocks, 256>>>(agg, bias0, h);

    // ---------- layers 1,2: GATv2(64 -> 64, H=2, mean) ----------
    for (int L = 0; L < 2; L++) {
        const float* Wl   = Wl1   + (size_t)L * 64 * 128;
        const float* bl   = bl1   + (size_t)L * 128;
        const float* Wr   = Wr1   + (size_t)L * 64 * 128;
        const float* br   = br1   + (size_t)L * 128;
        const float* We   = We1   + (size_t)L * FEDGE * 128;
        const float* att  = att1  + (size_t)L * 2 * 64;
        const float* bias = bias1 + (size_t)L * 64;
        float* outp = (L == 1) ? (float*)d_out : h;

        init_kernel<<<2048, 256>>>(agg, NN * 128, mx, den);
        transform_kernel<<<nodeBlocks, 128>>>(h, 64, 1, Wl, bl, Wr, br, 128, xl, xr);
        edge_logit_kernel<<<edgeBlocks, 256>>>(xl, xr, src, dst, ea, We, att, 128, 64, ex, mx);
        exp_kernel<<<expBlocks, 256>>>(dst, mx, ex, den);
        agg_kernel<<<edgeBlocks, 256>>>(xl, src, dst, ex, den, 128, 64, agg);
        finalize_mean<<<finBlocks, 256>>>(agg, bias, outp);
    }
}

// round 2
// speedup vs baseline: 2.0902x; 2.0902x over previous
#include <cuda_runtime.h>
#include <math.h>

#define NN 100000
#define EE 1600000
#define FNODE 79
#define FEDGE 10

// ---------------- scratch (device globals; no allocation) ----------------
__device__ float g_xl[NN * 128];
__device__ float g_xr[NN * 128];
__device__ float g_h[NN * 64];
__device__ int   g_deg[NN];
__device__ int   g_part[NN];
__device__ int   g_bsum[512];
__device__ int   g_off[NN + 1];
__device__ int   g_pos[NN];
__device__ int   g_eidx[EE];

// ================= CSR build =================
__global__ void zero_deg_kernel(int* deg) {
    int i = blockIdx.x * blockDim.x + threadIdx.x;
    if (i < NN) deg[i] = 0;
}

__global__ void count_kernel(const int* __restrict__ dst, int* __restrict__ deg) {
    int e = blockIdx.x * blockDim.x + threadIdx.x;
    if (e < EE) atomicAdd(&deg[dst[e]], 1);
}

#define SCAN_B 256
__global__ void scan1_kernel(const int* __restrict__ deg, int* __restrict__ part,
                             int* __restrict__ bsum) {
    __shared__ int s[SCAN_B];
    int i = blockIdx.x * SCAN_B + threadIdx.x;
    int v = (i < NN) ? deg[i] : 0;
    s[threadIdx.x] = v;
    __syncthreads();
    for (int o = 1; o < SCAN_B; o <<= 1) {
        int t = (threadIdx.x >= o) ? s[threadIdx.x - o] : 0;
        __syncthreads();
        s[threadIdx.x] += t;
        __syncthreads();
    }
    if (i < NN) part[i] = s[threadIdx.x] - v;  // exclusive
    if (threadIdx.x == SCAN_B - 1) bsum[blockIdx.x] = s[threadIdx.x];
}

__global__ void scan2_kernel(int* __restrict__ bsum, int nb) {
    __shared__ int s[512];
    int t = threadIdx.x;
    int v = (t < nb) ? bsum[t] : 0;
    s[t] = v;
    __syncthreads();
    for (int o = 1; o < 512; o <<= 1) {
        int u = (t >= o) ? s[t - o] : 0;
        __syncthreads();
        s[t] += u;
        __syncthreads();
    }
    if (t < nb) bsum[t] = s[t] - v;  // exclusive
}

__global__ void scan3_kernel(const int* __restrict__ part, const int* __restrict__ bsum,
                             int* __restrict__ off, int* __restrict__ pos) {
    int i = blockIdx.x * blockDim.x + threadIdx.x;
    if (i < NN) {
        int o = part[i] + bsum[i / SCAN_B];
        off[i] = o;
        pos[i] = o;
    }
    if (i == 0) off[NN] = EE;
}

__global__ void scatter_kernel(const int* __restrict__ dst, int* __restrict__ pos,
                               int* __restrict__ eidx) {
    int e = blockIdx.x * blockDim.x + threadIdx.x;
    if (e < EE) {
        int p = atomicAdd(&pos[dst[e]], 1);
        eidx[p] = e;
    }
}

// ================= node transforms: xl = act(in)@Wl + bl ; xr likewise =================
#define TN 32
__global__ void transform_kernel(const float* __restrict__ in, int in_dim, int act,
                                 const float* __restrict__ Wl, const float* __restrict__ bl,
                                 const float* __restrict__ Wr, const float* __restrict__ br,
                                 int out_dim,
                                 float* __restrict__ xl, float* __restrict__ xr) {
    __shared__ float s_in[TN][FNODE + 1];
    int node0 = blockIdx.x * TN;
    int t = threadIdx.x;  // one output column per thread (blockDim.x == out_dim)

    int tot = TN * in_dim;
    for (int idx = t; idx < tot; idx += blockDim.x) {
        int n = idx / in_dim;
        int k = idx - n * in_dim;
        int g = node0 + n;
        float v = (g < NN) ? in[(size_t)g * in_dim + k] : 0.f;
        if (act) v = (v > 0.f) ? v : 0.01f * v;
        s_in[n][k] = v;
    }
    __syncthreads();

    float accl[TN], accr[TN];
    float blv = bl[t], brv = br[t];
#pragma unroll
    for (int n = 0; n < TN; n++) { accl[n] = blv; accr[n] = brv; }

    for (int k = 0; k < in_dim; k++) {
        float wl = Wl[k * out_dim + t];
        float wr = Wr[k * out_dim + t];
#pragma unroll
        for (int n = 0; n < TN; n++) {
            float v = s_in[n][k];
            accl[n] = fmaf(v, wl, accl[n]);
            accr[n] = fmaf(v, wr, accr[n]);
        }
    }
#pragma unroll
    for (int n = 0; n < TN; n++) {
        int g = node0 + n;
        if (g < NN) {
            xl[(size_t)g * out_dim + t] = accl[n];
            xr[(size_t)g * out_dim + t] = accr[n];
        }
    }
}

// ================= fused per-node GATv2: logits + online softmax + aggregation =================
// one warp per destination node; CSR edge list; single xl[src] gather per edge
template <int HC, bool CONCAT>
__global__ void gat_node_kernel(const float* __restrict__ xl, const float* __restrict__ xr,
                                const int* __restrict__ src, const int* __restrict__ off,
                                const int* __restrict__ eidx, const float* __restrict__ ea,
                                const float* __restrict__ We, const float* __restrict__ att,
                                const float* __restrict__ bias, float* __restrict__ out) {
    constexpr int R = HC / 32;      // regs per lane for a full feature vector
    __shared__ float sWe[FEDGE * HC];
    int t = threadIdx.x;
    for (int i = t; i < FEDGE * HC; i += blockDim.x) sWe[i] = We[i];
    __syncthreads();

    int n = (blockIdx.x * blockDim.x + t) >> 5;
    int lane = t & 31;
    if (n >= NN) return;

    float xrv[R], attv[R];
#pragma unroll
    for (int r = 0; r < R; r++) {
        int c = lane + 32 * r;
        xrv[r] = xr[(size_t)n * HC + c];
        attv[r] = att[c];
    }

    float m0 = -INFINITY, m1 = -INFINITY, d0 = 0.f, d1 = 0.f;
    float acc[R];
#pragma unroll
    for (int r = 0; r < R; r++) acc[r] = 0.f;

    int j0 = off[n], j1 = off[n + 1];
    for (int j = j0; j < j1; j++) {
        int e = eidx[j];
        int s = src[e];
        float av = (lane < FEDGE) ? ea[(size_t)e * FEDGE + lane] : 0.f;
        float xlv[R];
#pragma unroll
        for (int r = 0; r < R; r++) xlv[r] = xl[(size_t)s * HC + lane + 32 * r];

        float a[FEDGE];
#pragma unroll
        for (int k = 0; k < FEDGE; k++) a[k] = __shfl_sync(0xffffffffu, av, k);

        float p0 = 0.f, p1 = 0.f;
#pragma unroll
        for (int r = 0; r < R; r++) {
            int c = lane + 32 * r;
            float ef = 0.f;
#pragma unroll
            for (int k = 0; k < FEDGE; k++) ef = fmaf(a[k], sWe[k * HC + c], ef);
            float mm = xlv[r] + xrv[r] + ef;
            mm = (mm > 0.f) ? mm : 0.2f * mm;    // GATv2 attention leaky relu
            float tv = mm * attv[r];
            if (r < R / 2) p0 += tv; else p1 += tv;
        }
#pragma unroll
        for (int o = 16; o > 0; o >>= 1) {
            p0 += __shfl_xor_sync(0xffffffffu, p0, o);
            p1 += __shfl_xor_sync(0xffffffffu, p1, o);
        }

        // online softmax update, per head
        float nm0 = fmaxf(m0, p0);
        float c0 = __expf(m0 - nm0), w0 = __expf(p0 - nm0);
        d0 = d0 * c0 + w0; m0 = nm0;
        float nm1 = fmaxf(m1, p1);
        float c1 = __expf(m1 - nm1), w1 = __expf(p1 - nm1);
        d1 = d1 * c1 + w1; m1 = nm1;
#pragma unroll
        for (int r = 0; r < R; r++) {
            float cs = (r < R / 2) ? c0 : c1;
            float ws = (r < R / 2) ? w0 : w1;
            acc[r] = acc[r] * cs + ws * xlv[r];
        }
    }

    d0 = fmaxf(d0, 1e-16f);
    d1 = fmaxf(d1, 1e-16f);

    if (CONCAT) {
#pragma unroll
        for (int r = 0; r < R; r++) {
            int c = lane + 32 * r;
            out[(size_t)n * HC + c] = acc[r] / ((r < R / 2) ? d0 : d1) + bias[c];
        }
    } else {
#pragma unroll
        for (int r = 0; r < R / 2; r++) {
            int c = lane + 32 * r;
            out[(size_t)n * 64 + c] = 0.5f * (acc[r] / d0 + acc[r + R / 2] / d1) + bias[c];
        }
    }
}

// ================= launch =================
extern "C" void kernel_launch(void* const* d_in, const int* in_sizes, int n_in,
                              void* d_out, int out_size) {
    const float* x    = (const float*)d_in[0];
    const int*   ei   = (const int*)d_in[1];
    const float* ea   = (const float*)d_in[2];
    const float* Wl0  = (const float*)d_in[3];
    const float* bl0  = (const float*)d_in[4];
    const float* Wr0  = (const float*)d_in[5];
    const float* br0  = (const float*)d_in[6];
    const float* We0  = (const float*)d_in[7];
    const float* att0 = (const float*)d_in[8];
    const float* bias0= (const float*)d_in[9];
    const float* Wl1  = (const float*)d_in[10];
    const float* bl1  = (const float*)d_in[11];
    const float* Wr1  = (const float*)d_in[12];
    const float* br1  = (const float*)d_in[13];
    const float* We1  = (const float*)d_in[14];
    const float* att1 = (const float*)d_in[15];
    const float* bias1= (const float*)d_in[16];

    const int* src = ei;
    const int* dst = ei + EE;

    float *xl, *xr, *h;
    int *deg, *part, *bsum, *off, *pos, *eidx;
    cudaGetSymbolAddress((void**)&xl,   g_xl);
    cudaGetSymbolAddress((void**)&xr,   g_xr);
    cudaGetSymbolAddress((void**)&h,    g_h);
    cudaGetSymbolAddress((void**)&deg,  g_deg);
    cudaGetSymbolAddress((void**)&part, g_part);
    cudaGetSymbolAddress((void**)&bsum, g_bsum);
    cudaGetSymbolAddress((void**)&off,  g_off);
    cudaGetSymbolAddress((void**)&pos,  g_pos);
    cudaGetSymbolAddress((void**)&eidx, g_eidx);

    const int nodeTBlocks = (NN + TN - 1) / TN;          // 3125
    const int edgeTBlocks = (EE + 255) / 256;
    const int scanBlocks  = (NN + SCAN_B - 1) / SCAN_B;  // 391
    const int nodeWBlocks = (NN + 7) / 8;                // warp per node, 8 warps/block

    // ---------- CSR build (by destination) ----------
    zero_deg_kernel<<<(NN + 255) / 256, 256>>>(deg);
    count_kernel<<<edgeTBlocks, 256>>>(dst, deg);
    scan1_kernel<<<scanBlocks, SCAN_B>>>(deg, part, bsum);
    scan2_kernel<<<1, 512>>>(bsum, scanBlocks);
    scan3_kernel<<<(NN + 255) / 256, 256>>>(part, bsum, off, pos);
    scatter_kernel<<<edgeTBlocks, 256>>>(dst, pos, eidx);

    // ---------- layer 0: GATv2(79 -> 32, H=2, concat) -> width 64 ----------
    transform_kernel<<<nodeTBlocks, 64>>>(x, FNODE, 0, Wl0, bl0, Wr0, br0, 64, xl, xr);
    gat_node_kernel<64, true><<<nodeWBlocks, 256>>>(xl, xr, src, off, eidx, ea, We0, att0, bias0, h);

    // ---------- layers 1,2: GATv2(64 -> 64, H=2, mean) ----------
    for (int L = 0; L < 2; L++) {
        const float* Wl   = Wl1   + (size_t)L * 64 * 128;
        const float* bl   = bl1   + (size_t)L * 128;
        const float* Wr   = Wr1   + (size_t)L * 64 * 128;
        const float* br   = br1   + (size_t)L * 128;
        const float* We   = We1   + (size_t)L * FEDGE * 128;
        const float* att  = att1  + (size_t)L * 2 * 64;
        const float* bias = bias1 + (size_t)L * 64;
        float* outp = (L == 1) ? (float*)d_out : h;

        transform_kernel<<<nodeTBlocks, 128>>>(h, 64, 1, Wl, bl, Wr, br, 128, xl, xr);
        gat_node_kernel<128, false><<<nodeWBlocks, 256>>>(xl, xr, src, off, eidx, ea, We, att, bias, outp);
    }
}